// round 3
// baseline (speedup 1.0000x reference)
#include <cuda_runtime.h>
#include <math.h>
#include <cstdint>

// Problem constants
#define BATCH 2
#define TSEQ  2048
#define DMODEL 1024
#define NHEADS 16
#define HDIM  64
#define ROWS (BATCH * TSEQ)          // 4096
#define QKV_N (3 * DMODEL)           // 3072

// ---------------- scratch (no allocation allowed) ----------------
__device__ float g_qkv[ROWS * QKV_N];               // [B*T, 3*D]
__device__ float g_q[BATCH * NHEADS * TSEQ * HDIM]; // [B,H,T,Dh]
__device__ float g_k[BATCH * NHEADS * TSEQ * HDIM];
__device__ float g_v[BATCH * NHEADS * TSEQ * HDIM];
__device__ float g_attn[ROWS * DMODEL];             // [B*T, D]
__device__ float g_cs[TSEQ * 32 * 2];               // cos,sin per (t, freq)

// ================= helpers =================
__device__ __forceinline__ uint32_t s2u(const void* p) {
    uint32_t a;
    asm("{ .reg .u64 t; cvta.to.shared.u64 t, %1; cvt.u32.u64 %0, t; }"
        : "=r"(a) : "l"(p));
    return a;
}

__device__ __forceinline__ uint32_t f2tf32(float f) {
    uint32_t r;
    asm("cvt.rna.tf32.f32 %0, %1;" : "=r"(r) : "f"(f));
    return r;
}

__device__ __forceinline__ void cp16(uint32_t dst, const void* src) {
    asm volatile("cp.async.cg.shared.global [%0], [%1], 16;" :: "r"(dst), "l"(src));
}

__device__ __forceinline__ void mma_m16n8k8_tf32(float* d, const uint32_t* a, const uint32_t* b) {
    asm volatile(
        "mma.sync.aligned.m16n8k8.row.col.f32.tf32.tf32.f32 "
        "{%0,%1,%2,%3}, {%4,%5,%6,%7}, {%8,%9}, {%0,%1,%2,%3};"
        : "+f"(d[0]), "+f"(d[1]), "+f"(d[2]), "+f"(d[3])
        : "r"(a[0]), "r"(a[1]), "r"(a[2]), "r"(a[3]), "r"(b[0]), "r"(b[1]));
}

// ============ tf32 mma.sync GEMM: C[M,NCOLS] = A[M,1024] @ W[NCOLS,1024]^T + bias ============
// CTA tile 128x128, 8 warps -> warp tile 32x64 (warp grid 4(M) x 2(N)).
// K-chunk 32 floats, 2-stage cp.async double buffer. smem row stride 36 (conflict-free).
#define KCH 32
#define NCHUNK (DMODEL / KCH)        // 32
#define SROW 36
#define TILE_F (128 * SROW)          // floats per (A or B) tile

__device__ __forceinline__ void ld_tile(const float* __restrict__ A,
                                        const float* __restrict__ W,
                                        int bm, int bn, int c,
                                        float* as, float* bs, int tid)
{
    #pragma unroll
    for (int i = 0; i < 4; i++) {
        const int idx = i * 256 + tid;       // 0..1023 : 16B chunks of 128x32f tile
        const int row = idx >> 3;
        const int q = idx & 7;
        const float* ga = A + (size_t)(bm + row) * DMODEL + c * KCH + q * 4;
        const float* gw = W + (size_t)(bn + row) * DMODEL + c * KCH + q * 4;
        cp16(s2u(as + row * SROW + q * 4), ga);
        cp16(s2u(bs + row * SROW + q * 4), gw);
    }
    asm volatile("cp.async.commit_group;" ::: "memory");
}

template<int NCOLS>
__global__ __launch_bounds__(256) void mma_gemm_kernel(const float* __restrict__ A,
                                                       const float* __restrict__ W,
                                                       const float* __restrict__ bias,
                                                       float* __restrict__ C)
{
    extern __shared__ float sm[];   // [2 stages][A tile | B tile]
    const int tid = threadIdx.x;
    const int wid = tid >> 5;
    const int lane = tid & 31;
    const int wm = wid & 3;          // warp M index (4)
    const int wn = wid >> 2;         // warp N index (2)
    const int gr = lane >> 2;        // 0..7
    const int tr = lane & 3;         // 0..3
    const int bm = blockIdx.y * 128;
    const int bn = blockIdx.x * 128;

    float acc[2][8][4];
    #pragma unroll
    for (int mi = 0; mi < 2; mi++)
        #pragma unroll
        for (int ni = 0; ni < 8; ni++)
            #pragma unroll
            for (int j = 0; j < 4; j++)
                acc[mi][ni][j] = 0.f;

    // prologue
    ld_tile(A, W, bm, bn, 0, sm, sm + TILE_F, tid);

    for (int c = 0; c < NCHUNK; c++) {
        const int st = c & 1;
        if (c + 1 < NCHUNK) {
            const int ns = (c + 1) & 1;
            ld_tile(A, W, bm, bn, c + 1, sm + ns * 2 * TILE_F, sm + ns * 2 * TILE_F + TILE_F, tid);
            asm volatile("cp.async.wait_group 1;" ::: "memory");
        } else {
            asm volatile("cp.async.wait_group 0;" ::: "memory");
        }
        __syncthreads();

        const float* as = sm + st * 2 * TILE_F + (wm * 32) * SROW;
        const float* bs = sm + st * 2 * TILE_F + TILE_F + (wn * 64) * SROW;

        #pragma unroll
        for (int kk = 0; kk < KCH; kk += 8) {
            uint32_t a[2][4];
            #pragma unroll
            for (int mi = 0; mi < 2; mi++) {
                const float* ap = as + (mi * 16 + gr) * SROW + kk + tr;
                a[mi][0] = f2tf32(ap[0]);
                a[mi][1] = f2tf32(ap[8 * SROW]);
                a[mi][2] = f2tf32(ap[4]);
                a[mi][3] = f2tf32(ap[8 * SROW + 4]);
            }
            uint32_t b[8][2];
            #pragma unroll
            for (int ni = 0; ni < 8; ni++) {
                const float* bp = bs + (ni * 8 + gr) * SROW + kk + tr;
                b[ni][0] = f2tf32(bp[0]);
                b[ni][1] = f2tf32(bp[4]);
            }
            #pragma unroll
            for (int mi = 0; mi < 2; mi++)
                #pragma unroll
                for (int ni = 0; ni < 8; ni++)
                    mma_m16n8k8_tf32(acc[mi][ni], a[mi], b[ni]);
        }
        __syncthreads();
    }

    // epilogue: bias + store (float2)
    #pragma unroll
    for (int mi = 0; mi < 2; mi++) {
        const int r0 = bm + wm * 32 + mi * 16 + gr;
        #pragma unroll
        for (int ni = 0; ni < 8; ni++) {
            const int cc = bn + wn * 64 + ni * 8 + tr * 2;
            const float b0 = bias[cc], b1 = bias[cc + 1];
            float2 o0 = make_float2(acc[mi][ni][0] + b0, acc[mi][ni][1] + b1);
            float2 o1 = make_float2(acc[mi][ni][2] + b0, acc[mi][ni][3] + b1);
            *(float2*)(C + (size_t)r0 * NCOLS + cc) = o0;
            *(float2*)(C + (size_t)(r0 + 8) * NCOLS + cc) = o1;
        }
    }
}

#define GEMM_SMEM (2 * 2 * TILE_F * (int)sizeof(float))   // 73728 B

// ---------------- RoPE table ----------------
__global__ void rope_table_kernel()
{
    int idx = blockIdx.x * blockDim.x + threadIdx.x;
    if (idx >= TSEQ * 32) return;
    int t = idx >> 5;
    int j = idx & 31;
    float invf = powf(10000.0f, -((float)(2 * j) / 64.0f));
    float angle = (float)t * invf;
    double a = (double)angle;
    double s, c;
    sincos(a, &s, &c);
    g_cs[idx * 2 + 0] = (float)c;
    g_cs[idx * 2 + 1] = (float)s;
}

// ---------------- RoPE apply + transpose to [B,H,T,Dh] ----------------
__global__ void rope_apply_kernel()
{
    int idx = blockIdx.x * blockDim.x + threadIdx.x;
    if (idx >= BATCH * TSEQ * NHEADS * 32) return;
    int j = idx & 31;
    int h = (idx >> 5) & (NHEADS - 1);
    int t = (idx >> 9) & (TSEQ - 1);
    int b = idx >> 20;

    int row = b * TSEQ + t;
    const float* base = g_qkv + (size_t)row * QKV_N + h * HDIM;

    float c  = g_cs[(t * 32 + j) * 2 + 0];
    float sn = g_cs[(t * 32 + j) * 2 + 1];

    float q1 = base[j],          q2 = base[j + 32];
    float k1 = base[DMODEL + j], k2 = base[DMODEL + j + 32];

    size_t od = (((size_t)b * NHEADS + h) * TSEQ + t) * HDIM;
    g_q[od + j]      = q1 * c - q2 * sn;
    g_q[od + j + 32] = q2 * c + q1 * sn;
    g_k[od + j]      = k1 * c - k2 * sn;
    g_k[od + j + 32] = k2 * c + k1 * sn;
    g_v[od + j]      = base[2 * DMODEL + j];
    g_v[od + j + 32] = base[2 * DMODEL + j + 32];
}

// ---------------- flash attention (fp32, causal, online softmax) ----------------
#define BQ 128
#define BKV 32

__global__ __launch_bounds__(BQ) void flash_kernel()
{
    const int tid = threadIdx.x;
    const int qt = (gridDim.x - 1) - blockIdx.x;    // heaviest tiles first
    const int h = blockIdx.y;
    const int b = blockIdx.z;
    const int qi = qt * BQ + tid;

    const size_t bh = ((size_t)b * NHEADS + h) * TSEQ * HDIM;

    __shared__ float Ks[BKV * HDIM];
    __shared__ float Vs[BKV * HDIM];

    float4 q4[16];
    const float4* qp = (const float4*)(g_q + bh + (size_t)qi * HDIM);
    #pragma unroll
    for (int i = 0; i < 16; i++) q4[i] = qp[i];

    float acc[HDIM];
    #pragma unroll
    for (int d = 0; d < HDIM; d++) acc[d] = 0.f;
    float m = -INFINITY, l = 0.f;
    const float scale = 0.125f;

    const int ntiles = qt * (BQ / BKV) + (BQ / BKV);
    for (int t0 = 0; t0 < ntiles; t0++) {
        const int j0 = t0 * BKV;
        const float4* ksrc = (const float4*)(g_k + bh + (size_t)j0 * HDIM);
        const float4* vsrc = (const float4*)(g_v + bh + (size_t)j0 * HDIM);
        float4* kdst = (float4*)Ks;
        float4* vdst = (float4*)Vs;
        #pragma unroll
        for (int r = 0; r < 4; r++) {
            kdst[tid + BQ * r] = ksrc[tid + BQ * r];
            vdst[tid + BQ * r] = vsrc[tid + BQ * r];
        }
        __syncthreads();

        if (qi >= j0) {
            float s[BKV];
            float mt = m;
            #pragma unroll
            for (int j = 0; j < BKV; j++) {
                const float4* kr = (const float4*)(Ks + j * HDIM);
                float sum = 0.f;
                #pragma unroll
                for (int d = 0; d < 16; d++) {
                    float4 kk = kr[d];
                    sum = fmaf(q4[d].x, kk.x, sum);
                    sum = fmaf(q4[d].y, kk.y, sum);
                    sum = fmaf(q4[d].z, kk.z, sum);
                    sum = fmaf(q4[d].w, kk.w, sum);
                }
                s[j] = sum * scale;
                if (j0 + j <= qi) mt = fmaxf(mt, s[j]);
            }
            float corr = expf(m - mt);
            m = mt;
            l *= corr;
            #pragma unroll
            for (int d = 0; d < HDIM; d++) acc[d] *= corr;

            #pragma unroll
            for (int j = 0; j < BKV; j++) {
                float p = (j0 + j <= qi) ? expf(s[j] - mt) : 0.f;
                l += p;
                const float4* vr = (const float4*)(Vs + j * HDIM);
                #pragma unroll
                for (int d = 0; d < 16; d++) {
                    float4 vv = vr[d];
                    acc[4 * d + 0] = fmaf(p, vv.x, acc[4 * d + 0]);
                    acc[4 * d + 1] = fmaf(p, vv.y, acc[4 * d + 1]);
                    acc[4 * d + 2] = fmaf(p, vv.z, acc[4 * d + 2]);
                    acc[4 * d + 3] = fmaf(p, vv.w, acc[4 * d + 3]);
                }
            }
        }
        __syncthreads();
    }

    const float inv_l = 1.f / l;
    float* op = g_attn + (((size_t)b * TSEQ + qi) * NHEADS + h) * HDIM;
    #pragma unroll
    for (int d = 0; d < HDIM; d += 4) {
        float4 o;
        o.x = acc[d + 0] * inv_l;
        o.y = acc[d + 1] * inv_l;
        o.z = acc[d + 2] * inv_l;
        o.w = acc[d + 3] * inv_l;
        *(float4*)(op + d) = o;
    }
}

// ---------------- launch ----------------
extern "C" void kernel_launch(void* const* d_in, const int* in_sizes, int n_in,
                              void* d_out, int out_size)
{
    const float* x      = (const float*)d_in[0];
    const float* qkv_w  = (const float*)d_in[1];
    const float* qkv_b  = (const float*)d_in[2];
    const float* proj_w = (const float*)d_in[3];
    const float* proj_b = (const float*)d_in[4];
    float* out = (float*)d_out;

    cudaFuncSetAttribute(mma_gemm_kernel<QKV_N>,
                         cudaFuncAttributeMaxDynamicSharedMemorySize, GEMM_SMEM);
    cudaFuncSetAttribute(mma_gemm_kernel<DMODEL>,
                         cudaFuncAttributeMaxDynamicSharedMemorySize, GEMM_SMEM);

    float* d_qkv;
    cudaGetSymbolAddress((void**)&d_qkv, g_qkv);
    float* d_attn;
    cudaGetSymbolAddress((void**)&d_attn, g_attn);

    // 1) QKV = x @ qkv_w^T + qkv_b  (tf32 mma.sync)
    mma_gemm_kernel<QKV_N><<<dim3(QKV_N / 128, ROWS / 128), 256, GEMM_SMEM>>>(
        x, qkv_w, qkv_b, d_qkv);

    // 2) RoPE cos/sin table
    rope_table_kernel<<<(TSEQ * 32 + 255) / 256, 256>>>();

    // 3) RoPE apply + layout to [B,H,T,Dh]
    rope_apply_kernel<<<(BATCH * TSEQ * NHEADS * 32) / 256, 256>>>();

    // 4) causal flash attention (fp32)
    flash_kernel<<<dim3(TSEQ / BQ, NHEADS, BATCH), BQ>>>();

    // 5) out = attn @ proj_w^T + proj_b  (tf32 mma.sync)
    mma_gemm_kernel<DMODEL><<<dim3(DMODEL / 128, ROWS / 128), 256, GEMM_SMEM>>>(
        d_attn, proj_w, proj_b, out);
}

// round 4
// speedup vs baseline: 1.1591x; 1.1591x over previous
#include <cuda_runtime.h>
#include <math.h>
#include <cstdint>

// Problem constants
#define BATCH 2
#define TSEQ  2048
#define DMODEL 1024
#define NHEADS 16
#define HDIM  64
#define ROWS (BATCH * TSEQ)          // 4096
#define QKV_N (3 * DMODEL)           // 3072

// ---------------- scratch (no allocation allowed) ----------------
__device__ float g_qkv[ROWS * QKV_N];               // [B*T, 3*D]
__device__ float g_q[BATCH * NHEADS * TSEQ * HDIM]; // [B,H,T,Dh]
__device__ float g_k[BATCH * NHEADS * TSEQ * HDIM];
__device__ float g_v[BATCH * NHEADS * TSEQ * HDIM];
__device__ float g_attn[ROWS * DMODEL];             // [B*T, D]
__device__ float g_cs[TSEQ * 32 * 2];               // cos,sin per (t, freq)

// ---------------- tiled fp32 GEMM: C = A[M,K] @ B[N,K]^T + bias ----------------
#define BM 128
#define BN 128
#define BKD 8
#define TM 8
#define TN 8

template<int M, int N, int K>
__device__ __forceinline__ void gemm_body(const float* __restrict__ A,
                                          const float* __restrict__ B,
                                          const float* __restrict__ bias,
                                          float* __restrict__ C)
{
    __shared__ float As[BKD][BM];
    __shared__ float Bs[BKD][BN];

    const int tid = threadIdx.x;           // 256 threads
    const int tx = tid & 15;               // col group
    const int ty = tid >> 4;               // row group
    const int bm = blockIdx.y * BM;
    const int bn = blockIdx.x * BN;

    const int lrow = tid >> 1;             // 0..127
    const int lk4  = (tid & 1) * 4;        // 0 or 4

    const float* Aptr = A + (size_t)(bm + lrow) * K + lk4;
    const float* Bptr = B + (size_t)(bn + lrow) * K + lk4;

    float acc[TM][TN];
    #pragma unroll
    for (int m = 0; m < TM; m++)
        #pragma unroll
        for (int n = 0; n < TN; n++)
            acc[m][n] = 0.f;

    for (int k0 = 0; k0 < K; k0 += BKD) {
        float4 av = *(const float4*)(Aptr + k0);
        float4 bv = *(const float4*)(Bptr + k0);
        As[lk4 + 0][lrow] = av.x; As[lk4 + 1][lrow] = av.y;
        As[lk4 + 2][lrow] = av.z; As[lk4 + 3][lrow] = av.w;
        Bs[lk4 + 0][lrow] = bv.x; Bs[lk4 + 1][lrow] = bv.y;
        Bs[lk4 + 2][lrow] = bv.z; Bs[lk4 + 3][lrow] = bv.w;
        __syncthreads();

        #pragma unroll
        for (int k = 0; k < BKD; k++) {
            float ra[TM], rb[TN];
            float4 a0 = *(const float4*)&As[k][ty * TM];
            float4 a1 = *(const float4*)&As[k][ty * TM + 4];
            ra[0]=a0.x; ra[1]=a0.y; ra[2]=a0.z; ra[3]=a0.w;
            ra[4]=a1.x; ra[5]=a1.y; ra[6]=a1.z; ra[7]=a1.w;
            float4 b0 = *(const float4*)&Bs[k][tx * TN];
            float4 b1 = *(const float4*)&Bs[k][tx * TN + 4];
            rb[0]=b0.x; rb[1]=b0.y; rb[2]=b0.z; rb[3]=b0.w;
            rb[4]=b1.x; rb[5]=b1.y; rb[6]=b1.z; rb[7]=b1.w;
            #pragma unroll
            for (int m = 0; m < TM; m++)
                #pragma unroll
                for (int n = 0; n < TN; n++)
                    acc[m][n] = fmaf(ra[m], rb[n], acc[m][n]);
        }
        __syncthreads();
    }

    #pragma unroll
    for (int m = 0; m < TM; m++) {
        const int row = bm + ty * TM + m;
        float* cp = C + (size_t)row * N + bn + tx * TN;
        const float* bp = bias + bn + tx * TN;
        #pragma unroll
        for (int n = 0; n < TN; n += 4) {
            float4 o;
            o.x = acc[m][n + 0] + bp[n + 0];
            o.y = acc[m][n + 1] + bp[n + 1];
            o.z = acc[m][n + 2] + bp[n + 2];
            o.w = acc[m][n + 3] + bp[n + 3];
            *(float4*)(cp + n) = o;
        }
    }
}

__global__ __launch_bounds__(256) void qkv_gemm_kernel(const float* __restrict__ x,
                                                       const float* __restrict__ w,
                                                       const float* __restrict__ b)
{
    gemm_body<ROWS, QKV_N, DMODEL>(x, w, b, g_qkv);
}

__global__ __launch_bounds__(256) void proj_gemm_kernel(const float* __restrict__ w,
                                                        const float* __restrict__ b,
                                                        float* __restrict__ out)
{
    gemm_body<ROWS, DMODEL, DMODEL>(g_attn, w, b, out);
}

// ---------------- RoPE table ----------------
__global__ void rope_table_kernel()
{
    int idx = blockIdx.x * blockDim.x + threadIdx.x;
    if (idx >= TSEQ * 32) return;
    int t = idx >> 5;
    int j = idx & 31;
    float invf = powf(10000.0f, -((float)(2 * j) / 64.0f));
    float angle = (float)t * invf;
    double a = (double)angle;
    double s, c;
    sincos(a, &s, &c);
    g_cs[idx * 2 + 0] = (float)c;
    g_cs[idx * 2 + 1] = (float)s;
}

// ---------------- RoPE apply + transpose to [B,H,T,Dh] ----------------
__global__ void rope_apply_kernel()
{
    int idx = blockIdx.x * blockDim.x + threadIdx.x;
    if (idx >= BATCH * TSEQ * NHEADS * 32) return;
    int j = idx & 31;
    int h = (idx >> 5) & (NHEADS - 1);
    int t = (idx >> 9) & (TSEQ - 1);
    int b = idx >> 20;

    int row = b * TSEQ + t;
    const float* base = g_qkv + (size_t)row * QKV_N + h * HDIM;

    float c  = g_cs[(t * 32 + j) * 2 + 0];
    float sn = g_cs[(t * 32 + j) * 2 + 1];

    float q1 = base[j],          q2 = base[j + 32];
    float k1 = base[DMODEL + j], k2 = base[DMODEL + j + 32];

    size_t od = (((size_t)b * NHEADS + h) * TSEQ + t) * HDIM;
    g_q[od + j]      = q1 * c - q2 * sn;
    g_q[od + j + 32] = q2 * c + q1 * sn;
    g_k[od + j]      = k1 * c - k2 * sn;
    g_k[od + j + 32] = k2 * c + k1 * sn;
    g_v[od + j]      = base[2 * DMODEL + j];
    g_v[od + j + 32] = base[2 * DMODEL + j + 32];
}

// ---------------- flash attention v2 ----------------
// 2 threads per q-row (each owns 32 dims). 256 threads/CTA, BQ=128 rows.
// 8-key subtiles keep scores in regs. K/V halves bank-skewed in smem.
#define BQ 128
#define BKV 32
#define SB 8
#define HB_OFF 1028     // floats: 1024 + 4 (16B skew -> conflict-free dual-broadcast)

__global__ __launch_bounds__(256) void flash_kernel()
{
    const int tid = threadIdx.x;
    const int r = tid >> 1;                         // q-row within CTA
    const int half = tid & 1;                       // dim half
    const int qt = (gridDim.x - 1) - blockIdx.x;    // heaviest tiles first
    const int h = blockIdx.y;
    const int b = blockIdx.z;
    const int qi = qt * BQ + r;

    const size_t bh = ((size_t)b * NHEADS + h) * TSEQ * HDIM;

    __shared__ float smK[2 * 1024 + 4];
    __shared__ float smV[2 * 1024 + 4];

    // q half-row in registers (pre-scaled by 1/sqrt(Dh) * log2(e))
    const float pre = 0.125f * 1.4426950408889634f;
    float4 q4[8];
    {
        const float4* qp = (const float4*)(g_q + bh + (size_t)qi * HDIM + half * 32);
        #pragma unroll
        for (int i = 0; i < 8; i++) {
            float4 v = qp[i];
            v.x *= pre; v.y *= pre; v.z *= pre; v.w *= pre;
            q4[i] = v;
        }
    }

    float acc[32];
    #pragma unroll
    for (int d = 0; d < 32; d++) acc[d] = 0.f;
    float m = -INFINITY, l = 0.f;

    const int hoff = half ? HB_OFF : 0;
    const int ntiles = (qt + 1) * (BQ / BKV);

    for (int t0 = 0; t0 < ntiles; t0++) {
        const int j0 = t0 * BKV;
        // cooperative K/V tile load with half-split + 16B skew
        {
            const float4* ksrc = (const float4*)(g_k + bh + (size_t)j0 * HDIM);
            const float4* vsrc = (const float4*)(g_v + bh + (size_t)j0 * HDIM);
            #pragma unroll
            for (int i = 0; i < 2; i++) {
                const int idx = i * 256 + tid;       // 0..511 float4 of 32x64 tile
                const int j = idx >> 4;
                const int c = idx & 15;
                const int dst = (c < 8) ? (j * 32 + c * 4)
                                        : (HB_OFF + j * 32 + (c - 8) * 4);
                *(float4*)&smK[dst] = ksrc[idx];
                *(float4*)&smV[dst] = vsrc[idx];
            }
        }
        __syncthreads();

        if (qi >= j0) {   // warp-uniform (warps cover 16 aligned rows, pairs share qi)
            #pragma unroll
            for (int sb = 0; sb < BKV / SB; sb++) {
                const int jb = j0 + sb * SB;
                float s[SB];
                float mt = m;
                #pragma unroll
                for (int jj = 0; jj < SB; jj++) {
                    const float4* kr = (const float4*)&smK[hoff + (sb * SB + jj) * 32];
                    float s0 = 0.f, s1 = 0.f, s2 = 0.f, s3 = 0.f;
                    #pragma unroll
                    for (int i = 0; i < 8; i += 4) {
                        float4 k0 = kr[i], k1 = kr[i+1], k2 = kr[i+2], k3 = kr[i+3];
                        s0 = fmaf(q4[i].x,   k0.x, s0); s0 = fmaf(q4[i].y,   k0.y, s0);
                        s0 = fmaf(q4[i].z,   k0.z, s0); s0 = fmaf(q4[i].w,   k0.w, s0);
                        s1 = fmaf(q4[i+1].x, k1.x, s1); s1 = fmaf(q4[i+1].y, k1.y, s1);
                        s1 = fmaf(q4[i+1].z, k1.z, s1); s1 = fmaf(q4[i+1].w, k1.w, s1);
                        s2 = fmaf(q4[i+2].x, k2.x, s2); s2 = fmaf(q4[i+2].y, k2.y, s2);
                        s2 = fmaf(q4[i+2].z, k2.z, s2); s2 = fmaf(q4[i+2].w, k2.w, s2);
                        s3 = fmaf(q4[i+3].x, k3.x, s3); s3 = fmaf(q4[i+3].y, k3.y, s3);
                        s3 = fmaf(q4[i+3].z, k3.z, s3); s3 = fmaf(q4[i+3].w, k3.w, s3);
                    }
                    float part = (s0 + s1) + (s2 + s3);
                    float sj = part + __shfl_xor_sync(0xffffffffu, part, 1);
                    s[jj] = sj;
                    if (jb + jj <= qi) mt = fmaxf(mt, sj);
                }
                const float corr = exp2f(m - mt);   // m=-inf first subtile -> 0
                m = mt;
                l *= corr;
                #pragma unroll
                for (int d = 0; d < 32; d++) acc[d] *= corr;

                #pragma unroll
                for (int jj = 0; jj < SB; jj++) {
                    const float p = (jb + jj <= qi) ? exp2f(s[jj] - mt) : 0.f;
                    l += p;
                    const float4* vr = (const float4*)&smV[hoff + (sb * SB + jj) * 32];
                    #pragma unroll
                    for (int i = 0; i < 8; i++) {
                        float4 vv = vr[i];
                        acc[4*i + 0] = fmaf(p, vv.x, acc[4*i + 0]);
                        acc[4*i + 1] = fmaf(p, vv.y, acc[4*i + 1]);
                        acc[4*i + 2] = fmaf(p, vv.z, acc[4*i + 2]);
                        acc[4*i + 3] = fmaf(p, vv.w, acc[4*i + 3]);
                    }
                }
            }
        }
        __syncthreads();
    }

    // write O as [B,T,H,Dh] rows for the proj GEMM
    const float inv_l = 1.f / l;
    float* op = g_attn + (((size_t)b * TSEQ + qi) * NHEADS + h) * HDIM + half * 32;
    #pragma unroll
    for (int d = 0; d < 32; d += 4) {
        float4 o;
        o.x = acc[d + 0] * inv_l;
        o.y = acc[d + 1] * inv_l;
        o.z = acc[d + 2] * inv_l;
        o.w = acc[d + 3] * inv_l;
        *(float4*)(op + d) = o;
    }
}

// ---------------- launch ----------------
extern "C" void kernel_launch(void* const* d_in, const int* in_sizes, int n_in,
                              void* d_out, int out_size)
{
    const float* x      = (const float*)d_in[0];
    const float* qkv_w  = (const float*)d_in[1];
    const float* qkv_b  = (const float*)d_in[2];
    const float* proj_w = (const float*)d_in[3];
    const float* proj_b = (const float*)d_in[4];
    float* out = (float*)d_out;

    // 1) QKV = x @ qkv_w^T + qkv_b
    qkv_gemm_kernel<<<dim3(QKV_N / BN, ROWS / BM), 256>>>(x, qkv_w, qkv_b);

    // 2) RoPE cos/sin table
    rope_table_kernel<<<(TSEQ * 32 + 255) / 256, 256>>>();

    // 3) RoPE apply + layout to [B,H,T,Dh]
    rope_apply_kernel<<<(BATCH * TSEQ * NHEADS * 32) / 256, 256>>>();

    // 4) causal flash attention v2
    flash_kernel<<<dim3(TSEQ / BQ, NHEADS, BATCH), 256>>>();

    // 5) out = attn @ proj_w^T + proj_b
    proj_gemm_kernel<<<dim3(DMODEL / BN, ROWS / BM), 256>>>(proj_w, proj_b, out);
}